// round 14
// baseline (speedup 1.0000x reference)
#include <cuda_runtime.h>

// ---------------------------------------------------------------------------
// LTFGW on GB300 (sm_103a).
//   k1_dots: register-tiled GEMM (measured ~23us, unchanged).
//   k2_solver R13: COLUMN-split 2 lanes/pair. Lane r owns 5 template columns
//   (j = 5r..5r+4), all 17 rows: Kr[85], v[5], s[5]. True register demand
//   drops to ~130 (row-split variants demanded >=180 and spilled at every
//   cap: R6/R10 DRAM 8.8%, R13-fused 8.5%). Row 0 needs no replication.
//   kv_i closes with one commutative shfl per row (u_i bitwise-identical in
//   both lanes); s/v fully local. Es is per-thread scratch, [(i*5+c)*BT+tid],
//   conflict-free.
// ---------------------------------------------------------------------------

#define N_NODES 10000
#define DIM 128
#define DEG 16
#define M_LOC 17
#define T_TPL 10
#define K_TPL 10
#define TK 100
#define N_PAIRS (N_NODES * T_TPL)
#define N_OUTER 5
#define N_SINK 10

__device__ float g_D[N_NODES * TK];   // dot(x[n], tf[t,k])
__device__ float g_xsq[N_NODES];
__device__ float g_gsq[TK];

// ---------------- Stage 1: dots + norms (register-tiled, unchanged) --------
#define K1_NPB 32
#define K1_HALF 50
#define TF_STRIDE 129
#define X_STRIDE 36

__global__ void __launch_bounds__(128) k1_dots(const float* __restrict__ x,
                                               const float* __restrict__ tf) {
    __shared__ alignas(16) float xst[DIM * X_STRIDE];      // 18.4 KB
    __shared__ alignas(16) float tfs[K1_HALF * TF_STRIDE]; // 25.8 KB
    const int tid = threadIdx.x;
    const int nbase = blockIdx.x * K1_NPB;

    for (int idx = tid; idx < K1_NPB * DIM; idx += 128) {
        int nl = idx >> 7, e = idx & 127;
        int n = nbase + nl;
        xst[e * X_STRIDE + nl] = (n < N_NODES) ? x[n * DIM + e] : 0.f;
    }

    const int tkl = (tid < 100) ? (tid % 50) : 0;
    const int qh  = (tid < 100) ? (tid / 50) : 0;

    #pragma unroll 1
    for (int s = 0; s < 2; s++) {
        __syncthreads();
        for (int idx = tid; idx < K1_HALF * DIM; idx += 128) {
            int tkr = idx >> 7, e = idx & 127;
            tfs[tkr * TF_STRIDE + e] = tf[(s * K1_HALF + tkr) * DIM + e];
        }
        __syncthreads();

        if (s == 0 && tid >= 100) {
            for (int nl = tid - 100; nl < K1_NPB; nl += 28) {
                int n = nbase + nl;
                if (n < N_NODES) {
                    float acc = 0.f;
                    #pragma unroll 8
                    for (int e = 0; e < DIM; e++) {
                        float c = xst[e * X_STRIDE + nl];
                        acc += c * c;
                    }
                    g_xsq[n] = acc;
                }
            }
        }
        if (blockIdx.x == 0 && tid < K1_HALF) {
            float acc = 0.f;
            #pragma unroll 8
            for (int e = 0; e < DIM; e++) {
                float c = tfs[tid * TF_STRIDE + e];
                acc += c * c;
            }
            g_gsq[s * K1_HALF + tid] = acc;
        }
        if (tid < 100) {
            float acc[16];
            #pragma unroll
            for (int i = 0; i < 16; i++) acc[i] = 0.f;
            const float* tfp = tfs + tkl * TF_STRIDE;
            const int nlo = qh * 16;
            #pragma unroll 4
            for (int e = 0; e < DIM; e++) {
                float tv = tfp[e];
                const float4* xp = (const float4*)(xst + e * X_STRIDE + nlo);
                float4 a0 = xp[0], a1 = xp[1], a2 = xp[2], a3 = xp[3];
                acc[0]  += tv * a0.x; acc[1]  += tv * a0.y; acc[2]  += tv * a0.z; acc[3]  += tv * a0.w;
                acc[4]  += tv * a1.x; acc[5]  += tv * a1.y; acc[6]  += tv * a1.z; acc[7]  += tv * a1.w;
                acc[8]  += tv * a2.x; acc[9]  += tv * a2.y; acc[10] += tv * a2.z; acc[11] += tv * a2.w;
                acc[12] += tv * a3.x; acc[13] += tv * a3.y; acc[14] += tv * a3.z; acc[15] += tv * a3.w;
            }
            int tk = s * K1_HALF + tkl;
            #pragma unroll
            for (int i = 0; i < 16; i++) {
                int n = nbase + nlo + i;
                if (n < N_NODES) g_D[n * TK + tk] = acc[i];
            }
        }
    }
}

// ---------------- Stage 2: FGW solver, column-split 2 lanes/pair -----------
#define BT 128                 // threads per block
#define PPB 64                 // pairs per block

__global__ void __launch_bounds__(BT, 3) k2_solver(const int* __restrict__ edge_index,
                                                   const float* __restrict__ templates,
                                                   float* __restrict__ out) {
    __shared__ float Es[M_LOC * 5 * BT];              // 43520 B, [(i*5+c)*BT + tid]
    __shared__ float Cts[T_TPL * K_TPL * K_TPL];
    __shared__ float ctqs[TK];
    __shared__ float gsqs[TK];
    const int tid = threadIdx.x;
    const int r = tid & 1;                 // lane parity within pair
    const int pairlo = tid >> 1;
    const int pair = blockIdx.x * PPB + pairlo;

    for (int idx = tid; idx < T_TPL * K_TPL * K_TPL; idx += BT) Cts[idx] = templates[idx];
    for (int idx = tid; idx < TK; idx += BT) gsqs[idx] = g_gsq[idx];
    __syncthreads();
    for (int idx = tid; idx < TK; idx += BT) {
        int t = idx / K_TPL, j = idx - t * K_TPL;
        float s = 0.f;
        #pragma unroll
        for (int jp = 0; jp < K_TPL; jp++) { float c = Cts[t * 100 + j * 10 + jp]; s += c * c; }
        ctqs[idx] = s * 0.1f;
    }
    __syncthreads();
    if (pair >= N_PAIRS) return;           // tail is warp-aligned

    const int n = pair / T_TPL;
    const int t = pair - n * T_TPL;
    const int jlo = 5 * r;                 // own columns jlo..jlo+4
    const int joth = 5 - jlo;              // partner's first column

    float* ep = Es + tid;                  // element (i,c) at ep[(i*5+c)*BT]
    const float* ct = Cts + t * 100;

    float cqo[5];                          // own (Ct^2 q)_j
    #pragma unroll
    for (int c = 0; c < 5; c++) cqo[c] = ctqs[t * 10 + jlo + c];

    // ---- E = exp(-M): all 17 rows, own 5 columns ----
    {
        float gso[5];
        #pragma unroll
        for (int c = 0; c < 5; c++) gso[c] = gsqs[t * 10 + jlo + c];
        #pragma unroll
        for (int i = 0; i < M_LOC; i++) {
            int rr = (i == 0) ? n : edge_index[n * DEG + (i - 1)];
            float xsq = g_xsq[rr];
            const float* Dp = g_D + rr * TK + t * 10 + jlo;
            #pragma unroll
            for (int c = 0; c < 5; c++) {
                float Mij = (xsq + gso[c] - 2.f * Dp[c]) * (1.f / 128.f);
                ep[(i * 5 + c) * BT] = __expf(-Mij);
            }
        }
    }

    const float P   = 1.f / 17.f;
    const float P0c = 16.f / 17.f;
    const float Q   = 0.1f;

    float Kr[85];                          // Kr[i*5+c] = T(i, jlo+c)
    #pragma unroll
    for (int ic = 0; ic < 85; ic++) Kr[ic] = 1.f / 170.f;

    float v[5];

    #pragma unroll 1
    for (int outer = 0; outer < N_OUTER; outer++) {
        // ---- local stats: t0 (row 0), ac (colsum rows 1..16), own cols ----
        float t0[5], ac[5];
        #pragma unroll
        for (int c = 0; c < 5; c++) {
            t0[c] = Kr[c];
            float s = 0.f;
            #pragma unroll
            for (int i = 1; i < M_LOC; i++) s += Kr[i * 5 + c];
            ac[c] = s;
        }
        // ---- b_j = (t0_full @ Ct)_j, G0_j = (a_full @ Ct)_j for OWN j via
        //      symmetric partials: own-j partial + partner's partial (shfl) ----
        float w[5], w0[5];
        #pragma unroll
        for (int c = 0; c < 5; c++) {
            float bo = 0.f, go = 0.f;      // partials for own column jlo+c
            float bx = 0.f, gx = 0.f;      // partials for partner column joth+c
            #pragma unroll
            for (int cp = 0; cp < 5; cp++) {
                float co = ct[(jlo + c) * 10 + jlo + cp];
                float cx = ct[(joth + c) * 10 + jlo + cp];
                bo += t0[cp] * co;  go += ac[cp] * co;
                bx += t0[cp] * cx;  gx += ac[cp] * cx;
            }
            float b  = bo + __shfl_xor_sync(0xffffffffu, bx, 1);
            float G0 = go + __shfl_xor_sync(0xffffffffu, gx, 1);
            w[c]  = __expf(-2.f * (P   + cqo[c] - 2.f * b));
            w0[c] = __expf(-2.f * (P0c + cqo[c] - 2.f * G0));
        }
        // ---- Gibbs kernel: K = T * E * w (w0 on row 0) ----
        #pragma unroll
        for (int c = 0; c < 5; c++) Kr[c] *= ep[c * BT] * w0[c];
        #pragma unroll
        for (int i = 1; i < M_LOC; i++) {
            #pragma unroll
            for (int c = 0; c < 5; c++)
                Kr[i * 5 + c] *= ep[(i * 5 + c) * BT] * w[c];
        }
        // ---- Sinkhorn (primal), v starts at 1 ----
        #pragma unroll
        for (int c = 0; c < 5; c++) v[c] = 1.f;
        #pragma unroll 1
        for (int it = 0; it < N_SINK - 1; it++) {
            float s[5];
            #pragma unroll
            for (int c = 0; c < 5; c++) s[c] = 0.f;
            #pragma unroll
            for (int i = 0; i < M_LOC; i++) {
                float kvp = 0.f;
                #pragma unroll
                for (int c = 0; c < 5; c++) kvp += Kr[i * 5 + c] * v[c];
                float kv = kvp + __shfl_xor_sync(0xffffffffu, kvp, 1);
                float u = __fdividef(P, kv);   // bitwise-identical in both lanes
                #pragma unroll
                for (int c = 0; c < 5; c++) s[c] += Kr[i * 5 + c] * u;
            }
            #pragma unroll
            for (int c = 0; c < 5; c++) v[c] = __fdividef(Q, s[c]);   // local!
        }
        // ---- last Sinkhorn iter: fold u into K on the fly, then v ----
        {
            float s[5];
            #pragma unroll
            for (int c = 0; c < 5; c++) s[c] = 0.f;
            #pragma unroll
            for (int i = 0; i < M_LOC; i++) {
                float kvp = 0.f;
                #pragma unroll
                for (int c = 0; c < 5; c++) kvp += Kr[i * 5 + c] * v[c];
                float kv = kvp + __shfl_xor_sync(0xffffffffu, kvp, 1);
                float u = __fdividef(P, kv);
                #pragma unroll
                for (int c = 0; c < 5; c++) {
                    float kru = Kr[i * 5 + c] * u;   // = K*u, reused for s and T
                    s[c] += kru;
                    Kr[i * 5 + c] = kru;
                }
            }
            #pragma unroll
            for (int c = 0; c < 5; c++) v[c] = __fdividef(Q, s[c]);
            #pragma unroll
            for (int i = 0; i < M_LOC; i++) {
                #pragma unroll
                for (int c = 0; c < 5; c++) Kr[i * 5 + c] *= v[c];
            }
        }
    }

    // ---- objective: sum T_ij (0.5 M_ij + 0.5(constC_ij - 2 G_ij)) ----
    float t0[5], ac[5];
    #pragma unroll
    for (int c = 0; c < 5; c++) {
        t0[c] = Kr[c];
        float s = 0.f;
        #pragma unroll
        for (int i = 1; i < M_LOC; i++) s += Kr[i * 5 + c];
        ac[c] = s;
    }
    float obj = 0.f;
    #pragma unroll
    for (int c = 0; c < 5; c++) {
        float bo = 0.f, go = 0.f, bx = 0.f, gx = 0.f;
        #pragma unroll
        for (int cp = 0; cp < 5; cp++) {
            float co = ct[(jlo + c) * 10 + jlo + cp];
            float cx = ct[(joth + c) * 10 + jlo + cp];
            bo += t0[cp] * co;  go += ac[cp] * co;
            bx += t0[cp] * cx;  gx += ac[cp] * cx;
        }
        float b  = bo + __shfl_xor_sync(0xffffffffu, bx, 1);
        float G0 = go + __shfl_xor_sync(0xffffffffu, gx, 1);
        float M0 = -__logf(ep[c * BT]);
        obj += Kr[c] * (0.5f * M0 + 0.5f * (P0c + cqo[c] - 2.f * G0));
        float cc = 0.5f * (P + cqo[c] - 2.f * b);
        #pragma unroll
        for (int i = 1; i < M_LOC; i++) {
            float Mij = -__logf(ep[(i * 5 + c) * BT]);
            obj += Kr[i * 5 + c] * (0.5f * Mij + cc);
        }
    }
    obj += __shfl_xor_sync(0xffffffffu, obj, 1);
    if (r == 0) out[pair] = obj;
}

// ---------------- launch: kernel launches ONLY ----------------
extern "C" void kernel_launch(void* const* d_in, const int* in_sizes, int n_in,
                              void* d_out, int out_size) {
    const float* x    = (const float*)d_in[0];
    const int*   ei   = (const int*)d_in[1];     // row 0 = src
    const float* tmpl = (const float*)d_in[2];
    const float* tf   = (const float*)d_in[3];
    float* out = (float*)d_out;

    k1_dots<<<(N_NODES + K1_NPB - 1) / K1_NPB, 128>>>(x, tf);
    k2_solver<<<(N_PAIRS + PPB - 1) / PPB, BT>>>(ei, tmpl, out);
}